// round 1
// baseline (speedup 1.0000x reference)
#include <cuda_runtime.h>
#include <math.h>

#define T 11
#define N_ENT 100000
#define N_TX 100000
#define D 128
#define E_EDGES 500000
#define F_TX 394
#define CIN (F_TX + T * D)      /* 1802 */
#define MSG_STRIDE (T * D)      /* 1408 */
#define NEG_SLOPE 0.2f
#define LN_EPS 1e-5f

// ---------------- scratch (device globals; no allocs allowed) ----------------
__device__ float g_xw[(size_t)N_ENT * D];       // per-type xw = x @ lin_w
__device__ float g_as[N_ENT];
__device__ float g_ad[N_ENT];
__device__ float g_m[N_ENT];                    // segment max
__device__ float g_den[N_ENT];                  // segment sum of exp
__device__ float g_ex[E_EDGES + N_ENT];         // per-edge exp (edges + self loops)
__device__ float g_gat[(size_t)N_ENT * D];      // GAT out, then layernormed h in-place
__device__ float g_msgs[(size_t)N_TX * MSG_STRIDE];
__device__ float g_h1[(size_t)N_TX * D];
__device__ float g_h2[(size_t)N_TX * 64];

// ---------------- helpers ----------------
__device__ __forceinline__ void atomicMaxFloat(float* a, float v) {
    if (v >= 0.f) atomicMax((int*)a, __float_as_int(v));
    else          atomicMin((unsigned int*)a, __float_as_uint(v));
}

#define FMA4(ACC, S, B) \
    (ACC).x += (S) * (B).x; (ACC).y += (S) * (B).y; \
    (ACC).z += (S) * (B).z; (ACC).w += (S) * (B).w;

// ---------------- zero msgs buffer ----------------
__global__ void k_zero_msgs() {
    size_t n4 = (size_t)N_TX * MSG_STRIDE / 4;
    float4 z = make_float4(0.f, 0.f, 0.f, 0.f);
    for (size_t i = (size_t)blockIdx.x * blockDim.x + threadIdx.x; i < n4;
         i += (size_t)gridDim.x * blockDim.x)
        ((float4*)g_msgs)[i] = z;
}

// ---------------- per-type init: zero g_gat, m = -inf, den = 0 ----------------
__global__ void k_init() {
    int i = blockIdx.x * blockDim.x + threadIdx.x;
    int n4 = N_ENT * D / 4;
    float4 z = make_float4(0.f, 0.f, 0.f, 0.f);
    for (int j = i; j < n4; j += gridDim.x * blockDim.x) ((float4*)g_gat)[j] = z;
    if (i < N_ENT) { g_m[i] = -INFINITY; g_den[i] = 0.f; }
}

// ---------------- GEMM1: xw = emb[idx] @ W ; also a_s, a_d ----------------
// block = 256 (8 warps), each warp computes 8 rows (in pairs), W (64KB) in smem
__global__ void k_gemm1(const float* __restrict__ emb, const int* __restrict__ idx,
                        const float* __restrict__ W,
                        const float* __restrict__ att_s, const float* __restrict__ att_d) {
    extern __shared__ float Bs[];   // 128*128 floats
    int tid = threadIdx.x;
#pragma unroll
    for (int i = 0; i < 16; i++) {
        int l = tid + i * 256;      // float4 index (4096 total)
        ((float4*)Bs)[l] = ((const float4*)W)[l];
    }
    __syncthreads();

    int lane = tid & 31, w = tid >> 5;
    float4 aS = ((const float4*)att_s)[lane];
    float4 aD = ((const float4*)att_d)[lane];
    int base = blockIdx.x * 64 + w * 8;

    for (int it = 0; it < 4; it++) {
        int r0 = base + it * 2;
        int r1 = r0 + 1;
        if (r0 >= N_ENT) break;
        bool v1 = (r1 < N_ENT);
        int g0 = idx[r0];
        int g1 = v1 ? idx[r1] : g0;
        float4 x0 = ((const float4*)(emb + (size_t)g0 * D))[lane];
        float4 x1 = ((const float4*)(emb + (size_t)g1 * D))[lane];
        float xa0[4] = {x0.x, x0.y, x0.z, x0.w};
        float xa1[4] = {x1.x, x1.y, x1.z, x1.w};
        float4 acc0 = make_float4(0.f, 0.f, 0.f, 0.f);
        float4 acc1 = make_float4(0.f, 0.f, 0.f, 0.f);
#pragma unroll
        for (int k = 0; k < D; k++) {
            float4 b = ((float4*)Bs)[k * 32 + lane];
            float xk0 = __shfl_sync(0xffffffffu, xa0[k & 3], k >> 2);
            float xk1 = __shfl_sync(0xffffffffu, xa1[k & 3], k >> 2);
            FMA4(acc0, xk0, b);
            FMA4(acc1, xk1, b);
        }
        // store xw
        ((float4*)(g_xw + (size_t)r0 * D))[lane] = acc0;
        if (v1) ((float4*)(g_xw + (size_t)r1 * D))[lane] = acc1;
        // attention logits
        float s0 = acc0.x * aS.x + acc0.y * aS.y + acc0.z * aS.z + acc0.w * aS.w;
        float d0 = acc0.x * aD.x + acc0.y * aD.y + acc0.z * aD.z + acc0.w * aD.w;
        float s1 = acc1.x * aS.x + acc1.y * aS.y + acc1.z * aS.z + acc1.w * aS.w;
        float d1 = acc1.x * aD.x + acc1.y * aD.y + acc1.z * aD.z + acc1.w * aD.w;
#pragma unroll
        for (int off = 16; off; off >>= 1) {
            s0 += __shfl_xor_sync(0xffffffffu, s0, off);
            d0 += __shfl_xor_sync(0xffffffffu, d0, off);
            s1 += __shfl_xor_sync(0xffffffffu, s1, off);
            d1 += __shfl_xor_sync(0xffffffffu, d1, off);
        }
        if (lane == 0) {
            g_as[r0] = s0; g_ad[r0] = d0;
            if (v1) { g_as[r1] = s1; g_ad[r1] = d1; }
        }
    }
}

// ---------------- edge pass 1: segment max ----------------
__global__ void k_edge_max(const int* __restrict__ src, const int* __restrict__ dst) {
    int i = blockIdx.x * blockDim.x + threadIdx.x;
    if (i >= E_EDGES + N_ENT) return;
    int s, d;
    if (i < E_EDGES) { s = src[i]; d = dst[i]; } else { s = i - E_EDGES; d = s; }
    float e = g_as[s] + g_ad[d];
    e = (e > 0.f) ? e : e * NEG_SLOPE;
    atomicMaxFloat(&g_m[d], e);
}

// ---------------- edge pass 2: exp + segment sum ----------------
__global__ void k_edge_exp(const int* __restrict__ src, const int* __restrict__ dst) {
    int i = blockIdx.x * blockDim.x + threadIdx.x;
    if (i >= E_EDGES + N_ENT) return;
    int s, d;
    if (i < E_EDGES) { s = src[i]; d = dst[i]; } else { s = i - E_EDGES; d = s; }
    float e = g_as[s] + g_ad[d];
    e = (e > 0.f) ? e : e * NEG_SLOPE;
    float ex = expf(e - g_m[d]);
    g_ex[i] = ex;
    atomicAdd(&g_den[d], ex);
}

// ---------------- edge pass 3: weighted scatter of xw into g_gat ----------------
// one warp per edge; 32 lanes x float4 = 128 cols
__global__ void k_gat_scatter(const int* __restrict__ src, const int* __restrict__ dst) {
    int e = blockIdx.x * 8 + (threadIdx.x >> 5);
    if (e >= E_EDGES + N_ENT) return;
    int lane = threadIdx.x & 31;
    int s, d;
    if (e < E_EDGES) { s = src[e]; d = dst[e]; } else { s = e - E_EDGES; d = s; }
    float alpha = g_ex[e] / (g_den[d] + 1e-16f);
    float4 v = ((const float4*)(g_xw + (size_t)s * D))[lane];
    v.x *= alpha; v.y *= alpha; v.z *= alpha; v.w *= alpha;
    atomicAdd(((float4*)(g_gat + (size_t)d * D)) + lane, v);
}

// ---------------- layernorm (adds conv_bias first), in-place ----------------
__global__ void k_ln(const float* __restrict__ conv_bias,
                     const float* __restrict__ gamma, const float* __restrict__ beta) {
    int r = blockIdx.x * 8 + (threadIdx.x >> 5);
    if (r >= N_ENT) return;
    int lane = threadIdx.x & 31;
    float4 v = ((float4*)(g_gat + (size_t)r * D))[lane];
    float4 cb = ((const float4*)conv_bias)[lane];
    v.x += cb.x; v.y += cb.y; v.z += cb.z; v.w += cb.w;
    float sum = v.x + v.y + v.z + v.w;
#pragma unroll
    for (int off = 16; off; off >>= 1) sum += __shfl_xor_sync(0xffffffffu, sum, off);
    float mu = sum * (1.f / D);
    float4 dd = make_float4(v.x - mu, v.y - mu, v.z - mu, v.w - mu);
    float sq = dd.x * dd.x + dd.y * dd.y + dd.z * dd.z + dd.w * dd.w;
#pragma unroll
    for (int off = 16; off; off >>= 1) sq += __shfl_xor_sync(0xffffffffu, sq, off);
    float inv = rsqrtf(sq * (1.f / D) + LN_EPS);
    float4 gm = ((const float4*)gamma)[lane];
    float4 bt = ((const float4*)beta)[lane];
    float4 h;
    h.x = dd.x * inv * gm.x + bt.x;
    h.y = dd.y * inv * gm.y + bt.y;
    h.z = dd.z * inv * gm.z + bt.z;
    h.w = dd.w * inv * gm.w + bt.w;
    ((float4*)(g_gat + (size_t)r * D))[lane] = h;
}

// ---------------- scatter h[src] into msgs[dst] (original edges only) ----------------
__global__ void k_msg_scatter(const int* __restrict__ src, const int* __restrict__ dst,
                              int toff) {
    int e = blockIdx.x * 8 + (threadIdx.x >> 5);
    if (e >= E_EDGES) return;
    int lane = threadIdx.x & 31;
    int s = src[e], d = dst[e];
    float4 v = ((const float4*)(g_gat + (size_t)s * D))[lane];
    atomicAdd(((float4*)(g_msgs + (size_t)d * MSG_STRIDE + toff)) + lane, v);
}

// ---------------- classifier layer 1: h1 = relu([tx|msgs] @ w1 + b1) ----------------
// BM=64, BN=128, BK=32; thread micro-tile 8 rows x 4 cols
__global__ void k_h1(const float* __restrict__ tx, const float* __restrict__ w1,
                     const float* __restrict__ b1) {
    __shared__ float Ast[32 * 68];   // [kk][row] padded stride 68
    __shared__ float Bs[32 * 128];
    int tid = threadIdx.x;
    int lane = tid & 31;
    int rg = tid >> 5;
    int rb = blockIdx.x * 64;
    int r0 = rg * 8;
    float4 acc[8];
#pragma unroll
    for (int i = 0; i < 8; i++) acc[i] = make_float4(0.f, 0.f, 0.f, 0.f);

    for (int kc = 0; kc < CIN; kc += 32) {
        // stage A (64 rows x 32 k), coalesced along k
#pragma unroll
        for (int i = 0; i < 8; i++) {
            int l = tid + i * 256;
            int kk = l & 31;
            int rr = l >> 5;
            int k = kc + kk;
            int row = rb + rr;
            float v = 0.f;
            if (k < CIN && row < N_TX)
                v = (k < F_TX) ? tx[(size_t)row * F_TX + k]
                               : g_msgs[(size_t)row * MSG_STRIDE + (k - F_TX)];
            Ast[kk * 68 + rr] = v;
        }
        // stage B (32 k x 128 cols)
#pragma unroll
        for (int i = 0; i < 4; i++) {
            int l = tid + i * 256;   // float4 index
            int c4 = l & 31;
            int kk = l >> 5;
            int k = kc + kk;
            float4 bv = make_float4(0.f, 0.f, 0.f, 0.f);
            if (k < CIN) bv = ((const float4*)(w1 + (size_t)k * D))[c4];
            ((float4*)Bs)[kk * 32 + c4] = bv;
        }
        __syncthreads();
#pragma unroll
        for (int kk = 0; kk < 32; kk++) {
            float4 b = ((float4*)Bs)[kk * 32 + lane];
            float4 a0 = *(const float4*)&Ast[kk * 68 + r0];
            float4 a1 = *(const float4*)&Ast[kk * 68 + r0 + 4];
            FMA4(acc[0], a0.x, b); FMA4(acc[1], a0.y, b);
            FMA4(acc[2], a0.z, b); FMA4(acc[3], a0.w, b);
            FMA4(acc[4], a1.x, b); FMA4(acc[5], a1.y, b);
            FMA4(acc[6], a1.z, b); FMA4(acc[7], a1.w, b);
        }
        __syncthreads();
    }
    float4 bb = ((const float4*)b1)[lane];
#pragma unroll
    for (int i = 0; i < 8; i++) {
        int row = rb + r0 + i;
        if (row < N_TX) {
            float4 o;
            o.x = fmaxf(acc[i].x + bb.x, 0.f);
            o.y = fmaxf(acc[i].y + bb.y, 0.f);
            o.z = fmaxf(acc[i].z + bb.z, 0.f);
            o.w = fmaxf(acc[i].w + bb.w, 0.f);
            ((float4*)(g_h1 + (size_t)row * D))[lane] = o;
        }
    }
}

// ---------------- classifier layer 2: h2 = relu(h1 @ w2 + b2) ----------------
__global__ void k_h2(const float* __restrict__ w2, const float* __restrict__ b2) {
    __shared__ float Ws[128 * 64];
    int tid = threadIdx.x;
#pragma unroll
    for (int i = 0; i < 8; i++)
        ((float4*)Ws)[tid + i * 256] = ((const float4*)w2)[tid + i * 256];
    __syncthreads();
    int lane = tid & 31, w = tid >> 5;
    for (int rr = 0; rr < 4; rr++) {
        int r = blockIdx.x * 32 + rr * 8 + w;
        if (r >= N_TX) return;
        float4 x = ((const float4*)(g_h1 + (size_t)r * D))[lane];
        float xa[4] = {x.x, x.y, x.z, x.w};
        float a0 = 0.f, a1 = 0.f;
#pragma unroll
        for (int k = 0; k < 128; k++) {
            float xk = __shfl_sync(0xffffffffu, xa[k & 3], k >> 2);
            float2 wv = *(const float2*)&Ws[k * 64 + lane * 2];
            a0 += xk * wv.x;
            a1 += xk * wv.y;
        }
        float2 bb = *(const float2*)&b2[lane * 2];
        g_h2[(size_t)r * 64 + lane * 2]     = fmaxf(a0 + bb.x, 0.f);
        g_h2[(size_t)r * 64 + lane * 2 + 1] = fmaxf(a1 + bb.y, 0.f);
    }
}

// ---------------- classifier layer 3: out = h2 @ w3 + b3 ----------------
__global__ void k_h3(const float* __restrict__ w3, const float* __restrict__ b3,
                     float* __restrict__ out) {
    int r = blockIdx.x * 8 + (threadIdx.x >> 5);
    if (r >= N_TX) return;
    int lane = threadIdx.x & 31;
    float v = g_h2[(size_t)r * 64 + lane] * w3[lane]
            + g_h2[(size_t)r * 64 + 32 + lane] * w3[32 + lane];
#pragma unroll
    for (int off = 16; off; off >>= 1) v += __shfl_xor_sync(0xffffffffu, v, off);
    if (lane == 0) out[r] = v + b3[0];
}

// ---------------- launcher ----------------
extern "C" void kernel_launch(void* const* d_in, const int* in_sizes, int n_in,
                              void* d_out, int out_size) {
    const float* tx_x      = (const float*)d_in[0];
    const float* emb       = (const float*)d_in[1];
    const float* lin_w     = (const float*)d_in[2];
    const float* att_src   = (const float*)d_in[3];
    const float* att_dst   = (const float*)d_in[4];
    const float* conv_bias = (const float*)d_in[5];
    const float* ln_gamma  = (const float*)d_in[6];
    const float* ln_beta   = (const float*)d_in[7];
    const float* w1        = (const float*)d_in[8];
    const float* b1        = (const float*)d_in[9];
    const float* w2        = (const float*)d_in[10];
    const float* b2        = (const float*)d_in[11];
    const float* w3        = (const float*)d_in[12];
    const float* b3        = (const float*)d_in[13];
    const int* entity_idx  = (const int*)d_in[14];
    const int* edge_src    = (const int*)d_in[15];
    const int* edge_dst    = (const int*)d_in[16];
    float* out = (float*)d_out;

    cudaFuncSetAttribute(k_gemm1, cudaFuncAttributeMaxDynamicSharedMemorySize, 64 * 1024);

    k_zero_msgs<<<2048, 256>>>();

    for (int t = 0; t < T; t++) {
        const float* embt = emb + (size_t)t * N_ENT * D;
        const int* idxt = entity_idx + (size_t)t * N_ENT;
        const int* srct = edge_src + (size_t)t * E_EDGES;
        const int* dstt = edge_dst + (size_t)t * E_EDGES;

        k_gemm1<<<(N_ENT + 63) / 64, 256, 64 * 1024>>>(embt, idxt, lin_w, att_src, att_dst);
        k_init<<<(N_ENT + 255) / 256, 256>>>();
        k_edge_max<<<(E_EDGES + N_ENT + 255) / 256, 256>>>(srct, dstt);
        k_edge_exp<<<(E_EDGES + N_ENT + 255) / 256, 256>>>(srct, dstt);
        k_gat_scatter<<<(E_EDGES + N_ENT + 7) / 8, 256>>>(srct, dstt);
        k_ln<<<(N_ENT + 7) / 8, 256>>>(conv_bias, ln_gamma + t * D, ln_beta + t * D);
        k_msg_scatter<<<(E_EDGES + 7) / 8, 256>>>(srct, dstt, t * D);
    }

    k_h1<<<(N_TX + 63) / 64, 256>>>(tx_x, w1, b1);
    k_h2<<<(N_TX + 31) / 32, 256>>>(w2, b2);
    k_h3<<<(N_TX + 7) / 8, 256>>>(w3, b3, out);
}

// round 2
// speedup vs baseline: 1.2278x; 1.2278x over previous
#include <cuda_runtime.h>
#include <math.h>

#define T 11
#define N_ENT 100000
#define N_TX 100000
#define D 128
#define E_EDGES 500000
#define F_TX 394
#define CIN (F_TX + T * D)      /* 1802 */
#define MSG_STRIDE (T * D)      /* 1408 */
#define NEG_SLOPE 0.2f
#define LN_EPS 1e-5f

#define SCAN_BLK 1024
#define NBLK_SCAN ((N_ENT + SCAN_BLK - 1) / SCAN_BLK)   /* 98 */

// ---------------- scratch (device globals; no allocs allowed) ----------------
__device__ float g_xw[(size_t)N_ENT * D];       // per-type xw = x @ lin_w
__device__ float g_as[N_ENT];
__device__ float g_ad[N_ENT];
__device__ float g_h[(size_t)N_ENT * D];        // layernormed GAT output h
__device__ float g_msgs[(size_t)N_TX * MSG_STRIDE];
__device__ float g_h1[(size_t)N_TX * D];

// CSR scratch
__device__ int g_cnt[T * N_ENT];
__device__ int g_off[T * N_ENT];                // exclusive offsets per type
__device__ int g_cur[T * N_ENT];                // fill cursors
__device__ int g_csr[(size_t)T * E_EDGES];      // src node per CSR slot
__device__ int g_blksum[T * NBLK_SCAN];

// ---------------- helpers ----------------
__device__ __forceinline__ float leaky(float e) {
    return (e > 0.f) ? e : e * NEG_SLOPE;
}

#define FMA4(ACC, S, B) \
    (ACC).x += (S) * (B).x; (ACC).y += (S) * (B).y; \
    (ACC).z += (S) * (B).z; (ACC).w += (S) * (B).w;

// ================= CSR build =================
__global__ void k_zero_cnt() {
    int i = blockIdx.x * blockDim.x + threadIdx.x;
    if (i < T * N_ENT) g_cnt[i] = 0;
}

__global__ void k_hist(const int* __restrict__ dst) {
    int t = blockIdx.y;
    int i = blockIdx.x * blockDim.x + threadIdx.x;
    if (i < E_EDGES) {
        int d = dst[(size_t)t * E_EDGES + i];
        atomicAdd(&g_cnt[t * N_ENT + d], 1);
    }
}

__global__ void k_scan1() {
    __shared__ int s[SCAN_BLK];
    int t = blockIdx.y;
    int tid = threadIdx.x;
    int idx = blockIdx.x * SCAN_BLK + tid;
    int v = (idx < N_ENT) ? g_cnt[t * N_ENT + idx] : 0;
    s[tid] = v;
    __syncthreads();
#pragma unroll
    for (int off = 1; off < SCAN_BLK; off <<= 1) {
        int y = (tid >= off) ? s[tid - off] : 0;
        __syncthreads();
        s[tid] += y;
        __syncthreads();
    }
    if (idx < N_ENT) g_off[t * N_ENT + idx] = s[tid] - v;   // exclusive
    if (tid == SCAN_BLK - 1) g_blksum[t * NBLK_SCAN + blockIdx.x] = s[tid];
}

__global__ void k_scan2() {
    int t = blockIdx.x;
    if (threadIdx.x == 0) {
        int run = 0;
        for (int b = 0; b < NBLK_SCAN; b++) {
            int v = g_blksum[t * NBLK_SCAN + b];
            g_blksum[t * NBLK_SCAN + b] = run;
            run += v;
        }
    }
}

__global__ void k_scan3() {
    int t = blockIdx.y;
    int idx = blockIdx.x * SCAN_BLK + threadIdx.x;
    if (idx < N_ENT) {
        int v = g_off[t * N_ENT + idx] + g_blksum[t * NBLK_SCAN + blockIdx.x];
        g_off[t * N_ENT + idx] = v;
        g_cur[t * N_ENT + idx] = v;
    }
}

__global__ void k_fill(const int* __restrict__ src, const int* __restrict__ dst) {
    int t = blockIdx.y;
    int i = blockIdx.x * blockDim.x + threadIdx.x;
    if (i < E_EDGES) {
        int d = dst[(size_t)t * E_EDGES + i];
        int pos = atomicAdd(&g_cur[t * N_ENT + d], 1);
        g_csr[(size_t)t * E_EDGES + pos] = src[(size_t)t * E_EDGES + i];
    }
}

// ================= GEMM1: xw = emb[idx] @ W ; a_s, a_d =================
__global__ void k_gemm1(const float* __restrict__ emb, const int* __restrict__ idx,
                        const float* __restrict__ W,
                        const float* __restrict__ att_s, const float* __restrict__ att_d) {
    extern __shared__ float Bs[];   // 128*128 floats
    int tid = threadIdx.x;
#pragma unroll
    for (int i = 0; i < 16; i++) {
        int l = tid + i * 256;
        ((float4*)Bs)[l] = ((const float4*)W)[l];
    }
    __syncthreads();

    int lane = tid & 31, w = tid >> 5;
    float4 aS = ((const float4*)att_s)[lane];
    float4 aD = ((const float4*)att_d)[lane];
    int base = blockIdx.x * 64 + w * 8;

    for (int it = 0; it < 4; it++) {
        int r0 = base + it * 2;
        int r1 = r0 + 1;
        if (r0 >= N_ENT) break;
        bool v1 = (r1 < N_ENT);
        int g0 = idx[r0];
        int g1 = v1 ? idx[r1] : g0;
        float4 x0 = ((const float4*)(emb + (size_t)g0 * D))[lane];
        float4 x1 = ((const float4*)(emb + (size_t)g1 * D))[lane];
        float xa0[4] = {x0.x, x0.y, x0.z, x0.w};
        float xa1[4] = {x1.x, x1.y, x1.z, x1.w};
        float4 acc0 = make_float4(0.f, 0.f, 0.f, 0.f);
        float4 acc1 = make_float4(0.f, 0.f, 0.f, 0.f);
#pragma unroll
        for (int k = 0; k < D; k++) {
            float4 b = ((float4*)Bs)[k * 32 + lane];
            float xk0 = __shfl_sync(0xffffffffu, xa0[k & 3], k >> 2);
            float xk1 = __shfl_sync(0xffffffffu, xa1[k & 3], k >> 2);
            FMA4(acc0, xk0, b);
            FMA4(acc1, xk1, b);
        }
        ((float4*)(g_xw + (size_t)r0 * D))[lane] = acc0;
        if (v1) ((float4*)(g_xw + (size_t)r1 * D))[lane] = acc1;
        float s0 = acc0.x * aS.x + acc0.y * aS.y + acc0.z * aS.z + acc0.w * aS.w;
        float d0 = acc0.x * aD.x + acc0.y * aD.y + acc0.z * aD.z + acc0.w * aD.w;
        float s1 = acc1.x * aS.x + acc1.y * aS.y + acc1.z * aS.z + acc1.w * aS.w;
        float d1 = acc1.x * aD.x + acc1.y * aD.y + acc1.z * aD.z + acc1.w * aD.w;
#pragma unroll
        for (int off = 16; off; off >>= 1) {
            s0 += __shfl_xor_sync(0xffffffffu, s0, off);
            d0 += __shfl_xor_sync(0xffffffffu, d0, off);
            s1 += __shfl_xor_sync(0xffffffffu, s1, off);
            d1 += __shfl_xor_sync(0xffffffffu, d1, off);
        }
        if (lane == 0) {
            g_as[r0] = s0; g_ad[r0] = d0;
            if (v1) { g_as[r1] = s1; g_ad[r1] = d1; }
        }
    }
}

// ================= fused GAT: softmax + aggregate + bias + LN =================
// one warp per dst node
__global__ void k_gat(int t, const float* __restrict__ conv_bias,
                      const float* __restrict__ gamma, const float* __restrict__ beta) {
    int d = blockIdx.x * 8 + (threadIdx.x >> 5);
    if (d >= N_ENT) return;
    int lane = threadIdx.x & 31;
    int off0 = g_off[t * N_ENT + d];
    int off1 = (d + 1 < N_ENT) ? g_off[t * N_ENT + d + 1] : E_EDGES;
    const int* csr = g_csr + (size_t)t * E_EDGES;

    float ad = g_ad[d];
    float e_self = leaky(g_as[d] + ad);

    // pass 1: max
    float m = e_self;
    for (int j = off0 + lane; j < off1; j += 32)
        m = fmaxf(m, leaky(g_as[csr[j]] + ad));
#pragma unroll
    for (int off = 16; off; off >>= 1)
        m = fmaxf(m, __shfl_xor_sync(0xffffffffu, m, off));

    // pass 2: sum of exp
    float ssum = 0.f;
    for (int j = off0 + lane; j < off1; j += 32)
        ssum += expf(leaky(g_as[csr[j]] + ad) - m);
#pragma unroll
    for (int off = 16; off; off >>= 1)
        ssum += __shfl_xor_sync(0xffffffffu, ssum, off);
    float ex_self = expf(e_self - m);
    float inv = 1.f / (ssum + ex_self + 1e-16f);

    // pass 3: weighted aggregate (32 lanes x float4 = 128 cols)
    float a_self = ex_self * inv;
    float4 acc = ((const float4*)(g_xw + (size_t)d * D))[lane];
    acc.x *= a_self; acc.y *= a_self; acc.z *= a_self; acc.w *= a_self;
    for (int j = off0; j < off1; j++) {
        int s = csr[j];
        float a = expf(leaky(g_as[s] + ad) - m) * inv;
        float4 v = ((const float4*)(g_xw + (size_t)s * D))[lane];
        FMA4(acc, a, v);
    }

    // conv_bias + layernorm
    float4 cb = ((const float4*)conv_bias)[lane];
    acc.x += cb.x; acc.y += cb.y; acc.z += cb.z; acc.w += cb.w;
    float sum = acc.x + acc.y + acc.z + acc.w;
#pragma unroll
    for (int off = 16; off; off >>= 1) sum += __shfl_xor_sync(0xffffffffu, sum, off);
    float mu = sum * (1.f / D);
    float4 dd = make_float4(acc.x - mu, acc.y - mu, acc.z - mu, acc.w - mu);
    float sq = dd.x * dd.x + dd.y * dd.y + dd.z * dd.z + dd.w * dd.w;
#pragma unroll
    for (int off = 16; off; off >>= 1) sq += __shfl_xor_sync(0xffffffffu, sq, off);
    float invs = rsqrtf(sq * (1.f / D) + LN_EPS);
    float4 gm = ((const float4*)gamma)[lane];
    float4 bt = ((const float4*)beta)[lane];
    float4 h;
    h.x = dd.x * invs * gm.x + bt.x;
    h.y = dd.y * invs * gm.y + bt.y;
    h.z = dd.z * invs * gm.z + bt.z;
    h.w = dd.w * invs * gm.w + bt.w;
    ((float4*)(g_h + (size_t)d * D))[lane] = h;
}

// ================= msg gather: msgs[d, t*D:] = sum_{edges->d} h[src] =================
__global__ void k_msg(int t) {
    int d = blockIdx.x * 8 + (threadIdx.x >> 5);
    if (d >= N_TX) return;
    int lane = threadIdx.x & 31;
    int off0 = g_off[t * N_ENT + d];
    int off1 = (d + 1 < N_ENT) ? g_off[t * N_ENT + d + 1] : E_EDGES;
    const int* csr = g_csr + (size_t)t * E_EDGES;
    float4 acc = make_float4(0.f, 0.f, 0.f, 0.f);
    for (int j = off0; j < off1; j++) {
        int s = csr[j];
        float4 v = ((const float4*)(g_h + (size_t)s * D))[lane];
        acc.x += v.x; acc.y += v.y; acc.z += v.z; acc.w += v.w;
    }
    ((float4*)(g_msgs + (size_t)d * MSG_STRIDE + t * D))[lane] = acc;
}

// ================= classifier layer 1 =================
__global__ void k_h1(const float* __restrict__ tx, const float* __restrict__ w1,
                     const float* __restrict__ b1) {
    __shared__ float Ast[32 * 68];
    __shared__ float Bs[32 * 128];
    int tid = threadIdx.x;
    int lane = tid & 31;
    int rg = tid >> 5;
    int rb = blockIdx.x * 64;
    int r0 = rg * 8;
    float4 acc[8];
#pragma unroll
    for (int i = 0; i < 8; i++) acc[i] = make_float4(0.f, 0.f, 0.f, 0.f);

    for (int kc = 0; kc < CIN; kc += 32) {
#pragma unroll
        for (int i = 0; i < 8; i++) {
            int l = tid + i * 256;
            int kk = l & 31;
            int rr = l >> 5;
            int k = kc + kk;
            int row = rb + rr;
            float v = 0.f;
            if (k < CIN && row < N_TX)
                v = (k < F_TX) ? tx[(size_t)row * F_TX + k]
                               : g_msgs[(size_t)row * MSG_STRIDE + (k - F_TX)];
            Ast[kk * 68 + rr] = v;
        }
#pragma unroll
        for (int i = 0; i < 4; i++) {
            int l = tid + i * 256;
            int c4 = l & 31;
            int kk = l >> 5;
            int k = kc + kk;
            float4 bv = make_float4(0.f, 0.f, 0.f, 0.f);
            if (k < CIN) bv = ((const float4*)(w1 + (size_t)k * D))[c4];
            ((float4*)Bs)[kk * 32 + c4] = bv;
        }
        __syncthreads();
#pragma unroll
        for (int kk = 0; kk < 32; kk++) {
            float4 b = ((float4*)Bs)[kk * 32 + lane];
            float4 a0 = *(const float4*)&Ast[kk * 68 + r0];
            float4 a1 = *(const float4*)&Ast[kk * 68 + r0 + 4];
            FMA4(acc[0], a0.x, b); FMA4(acc[1], a0.y, b);
            FMA4(acc[2], a0.z, b); FMA4(acc[3], a0.w, b);
            FMA4(acc[4], a1.x, b); FMA4(acc[5], a1.y, b);
            FMA4(acc[6], a1.z, b); FMA4(acc[7], a1.w, b);
        }
        __syncthreads();
    }
    float4 bb = ((const float4*)b1)[lane];
#pragma unroll
    for (int i = 0; i < 8; i++) {
        int row = rb + r0 + i;
        if (row < N_TX) {
            float4 o;
            o.x = fmaxf(acc[i].x + bb.x, 0.f);
            o.y = fmaxf(acc[i].y + bb.y, 0.f);
            o.z = fmaxf(acc[i].z + bb.z, 0.f);
            o.w = fmaxf(acc[i].w + bb.w, 0.f);
            ((float4*)(g_h1 + (size_t)row * D))[lane] = o;
        }
    }
}

// ================= fused classifier layers 2+3 =================
__global__ void k_h23(const float* __restrict__ w2, const float* __restrict__ b2,
                      const float* __restrict__ w3, const float* __restrict__ b3,
                      float* __restrict__ out) {
    __shared__ float Ws[128 * 64];
    __shared__ float w3s[64];
    int tid = threadIdx.x;
#pragma unroll
    for (int i = 0; i < 8; i++)
        ((float4*)Ws)[tid + i * 256] = ((const float4*)w2)[tid + i * 256];
    if (tid < 64) w3s[tid] = w3[tid];
    __syncthreads();
    int lane = tid & 31, w = tid >> 5;
    for (int rr = 0; rr < 4; rr++) {
        int r = blockIdx.x * 32 + rr * 8 + w;
        if (r >= N_TX) return;
        float4 x = ((const float4*)(g_h1 + (size_t)r * D))[lane];
        float xa[4] = {x.x, x.y, x.z, x.w};
        float a0 = 0.f, a1 = 0.f;
#pragma unroll
        for (int k = 0; k < 128; k++) {
            float xk = __shfl_sync(0xffffffffu, xa[k & 3], k >> 2);
            float2 wv = *(const float2*)&Ws[k * 64 + lane * 2];
            a0 += xk * wv.x;
            a1 += xk * wv.y;
        }
        float2 bb = *(const float2*)&b2[lane * 2];
        float h0 = fmaxf(a0 + bb.x, 0.f);
        float h1v = fmaxf(a1 + bb.y, 0.f);
        float v = h0 * w3s[lane * 2] + h1v * w3s[lane * 2 + 1];
#pragma unroll
        for (int off = 16; off; off >>= 1) v += __shfl_xor_sync(0xffffffffu, v, off);
        if (lane == 0) out[r] = v + b3[0];
    }
}

// ================= launcher =================
extern "C" void kernel_launch(void* const* d_in, const int* in_sizes, int n_in,
                              void* d_out, int out_size) {
    const float* tx_x      = (const float*)d_in[0];
    const float* emb       = (const float*)d_in[1];
    const float* lin_w     = (const float*)d_in[2];
    const float* att_src   = (const float*)d_in[3];
    const float* att_dst   = (const float*)d_in[4];
    const float* conv_bias = (const float*)d_in[5];
    const float* ln_gamma  = (const float*)d_in[6];
    const float* ln_beta   = (const float*)d_in[7];
    const float* w1        = (const float*)d_in[8];
    const float* b1        = (const float*)d_in[9];
    const float* w2        = (const float*)d_in[10];
    const float* b2        = (const float*)d_in[11];
    const float* w3        = (const float*)d_in[12];
    const float* b3        = (const float*)d_in[13];
    const int* entity_idx  = (const int*)d_in[14];
    const int* edge_src    = (const int*)d_in[15];
    const int* edge_dst    = (const int*)d_in[16];
    float* out = (float*)d_out;

    cudaFuncSetAttribute(k_gemm1, cudaFuncAttributeMaxDynamicSharedMemorySize, 64 * 1024);

    // ---- CSR build (all types) ----
    k_zero_cnt<<<(T * N_ENT + 255) / 256, 256>>>();
    {
        dim3 g((E_EDGES + 255) / 256, T);
        k_hist<<<g, 256>>>(edge_dst);
    }
    {
        dim3 g(NBLK_SCAN, T);
        k_scan1<<<g, SCAN_BLK>>>();
        k_scan2<<<T, 32>>>();
        k_scan3<<<g, SCAN_BLK>>>();
    }
    {
        dim3 g((E_EDGES + 255) / 256, T);
        k_fill<<<g, 256>>>(edge_src, edge_dst);
    }

    // ---- per-type GAT pipeline ----
    for (int t = 0; t < T; t++) {
        const float* embt = emb + (size_t)t * N_ENT * D;
        const int* idxt = entity_idx + (size_t)t * N_ENT;
        k_gemm1<<<(N_ENT + 63) / 64, 256, 64 * 1024>>>(embt, idxt, lin_w, att_src, att_dst);
        k_gat<<<(N_ENT + 7) / 8, 256>>>(t, conv_bias, ln_gamma + t * D, ln_beta + t * D);
        k_msg<<<(N_TX + 7) / 8, 256>>>(t);
    }

    // ---- classifier ----
    k_h1<<<(N_TX + 63) / 64, 256>>>(tx_x, w1, b1);
    k_h23<<<(N_TX + 31) / 32, 256>>>(w2, b2, w3, b3, out);
}

// round 4
// speedup vs baseline: 1.8098x; 1.4739x over previous
#include <cuda_runtime.h>
#include <math.h>
#include <stdint.h>

#define T 11
#define N_ENT 100000
#define N_TX 100000
#define D 128
#define E_EDGES 500000
#define F_TX 394
#define COMB_K 1802
#define COMB_STRIDE 1824
#define NEG_SLOPE 0.2f
#define LN_EPS 1e-5f

#define SCAN_BLK 1024
#define NBLK_SCAN ((N_ENT + SCAN_BLK - 1) / SCAN_BLK)   /* 98 */

// ---------------- scratch (device globals; no allocs allowed) ----------------
__device__ float g_xw[(size_t)T * N_ENT * D];
__device__ float g_as[T * N_ENT];
__device__ float g_ad[T * N_ENT];
__device__ float g_h[(size_t)T * N_ENT * D];
__device__ float g_comb[(size_t)N_TX * COMB_STRIDE];   // [msgs 1408 | tx 394 | pad 22]
__device__ float g_h1[(size_t)N_TX * D];

__device__ int g_cnt[T * N_ENT];
__device__ int g_off[T * N_ENT];
__device__ int g_cur[T * N_ENT];
__device__ int g_csr[(size_t)T * E_EDGES];
__device__ int g_blksum[T * NBLK_SCAN];

// ---------------- helpers ----------------
__device__ __forceinline__ float leaky(float e) { return (e > 0.f) ? e : e * NEG_SLOPE; }

#define FMA4(ACC, S, B) \
    (ACC).x += (S) * (B).x; (ACC).y += (S) * (B).y; \
    (ACC).z += (S) * (B).z; (ACC).w += (S) * (B).w;

__device__ __forceinline__ void cp16(uint32_t s, const void* g) {
    asm volatile("cp.async.cg.shared.global [%0], [%1], 16;" :: "r"(s), "l"(g));
}
__device__ __forceinline__ void cp16z(uint32_t s, const void* g) {
    asm volatile("cp.async.cg.shared.global [%0], [%1], 16, 0;" :: "r"(s), "l"(g));
}
#define CP_COMMIT asm volatile("cp.async.commit_group;")
#define CP_WAIT0  asm volatile("cp.async.wait_group 0;")

__device__ __forceinline__ void mma8(float* c, const uint32_t* a, uint32_t b0, uint32_t b1) {
    asm volatile(
        "mma.sync.aligned.m16n8k8.row.col.f32.tf32.tf32.f32 "
        "{%0,%1,%2,%3}, {%4,%5,%6,%7}, {%8,%9}, {%0,%1,%2,%3};"
        : "+f"(c[0]), "+f"(c[1]), "+f"(c[2]), "+f"(c[3])
        : "r"(a[0]), "r"(a[1]), "r"(a[2]), "r"(a[3]), "r"(b0), "r"(b1));
}

__device__ __forceinline__ uint32_t f2tf(float x) {
    uint32_t r;
    asm("cvt.rna.tf32.f32 %0, %1;" : "=r"(r) : "f"(x));
    return r;
}
__device__ __forceinline__ void tfsplit(float x, uint32_t& hi, uint32_t& lo) {
    hi = f2tf(x);
    lo = f2tf(x - __uint_as_float(hi));
}

// ================= CSR build =================
__global__ void k_zero_cnt() {
    int i = blockIdx.x * blockDim.x + threadIdx.x;
    if (i < T * N_ENT) g_cnt[i] = 0;
}
__global__ void k_hist(const int* __restrict__ dst) {
    int t = blockIdx.y;
    int i = blockIdx.x * blockDim.x + threadIdx.x;
    if (i < E_EDGES) atomicAdd(&g_cnt[t * N_ENT + dst[(size_t)t * E_EDGES + i]], 1);
}
__global__ void k_scan1() {
    __shared__ int s[SCAN_BLK];
    int t = blockIdx.y, tid = threadIdx.x;
    int idx = blockIdx.x * SCAN_BLK + tid;
    int v = (idx < N_ENT) ? g_cnt[t * N_ENT + idx] : 0;
    s[tid] = v;
    __syncthreads();
#pragma unroll
    for (int off = 1; off < SCAN_BLK; off <<= 1) {
        int y = (tid >= off) ? s[tid - off] : 0;
        __syncthreads();
        s[tid] += y;
        __syncthreads();
    }
    if (idx < N_ENT) g_off[t * N_ENT + idx] = s[tid] - v;
    if (tid == SCAN_BLK - 1) g_blksum[t * NBLK_SCAN + blockIdx.x] = s[tid];
}
__global__ void k_scan2() {
    int t = blockIdx.x;
    if (threadIdx.x == 0) {
        int run = 0;
        for (int b = 0; b < NBLK_SCAN; b++) {
            int v = g_blksum[t * NBLK_SCAN + b];
            g_blksum[t * NBLK_SCAN + b] = run;
            run += v;
        }
    }
}
__global__ void k_scan3() {
    int t = blockIdx.y;
    int idx = blockIdx.x * SCAN_BLK + threadIdx.x;
    if (idx < N_ENT) {
        int v = g_off[t * N_ENT + idx] + g_blksum[t * NBLK_SCAN + blockIdx.x];
        g_off[t * N_ENT + idx] = v;
        g_cur[t * N_ENT + idx] = v;
    }
}
__global__ void k_fill(const int* __restrict__ src, const int* __restrict__ dst) {
    int t = blockIdx.y;
    int i = blockIdx.x * blockDim.x + threadIdx.x;
    if (i < E_EDGES) {
        int d = dst[(size_t)t * E_EDGES + i];
        int pos = atomicAdd(&g_cur[t * N_ENT + d], 1);
        g_csr[(size_t)t * E_EDGES + pos] = src[(size_t)t * E_EDGES + i];
    }
}

// ================= copy tx into combined buffer =================
__global__ void k_copytx(const float* __restrict__ tx) {
    int r = blockIdx.x * 8 + (threadIdx.x >> 5);
    if (r >= N_TX) return;
    int lane = threadIdx.x & 31;
    float* drow = g_comb + (size_t)r * COMB_STRIDE + 1408;
    const float* srow = tx + (size_t)r * F_TX;
    for (int c = lane; c < F_TX; c += 32) drow[c] = srow[c];
    int p = F_TX + lane;
    if (p < COMB_STRIDE - 1408) drow[p] = 0.f;
}

// ================= GEMM1 (3xTF32 mma): xw = emb[idx] @ W ; a_s, a_d =================
#define SA1 132
#define SB1 136
__global__ __launch_bounds__(256, 1) void k_gemm1(
    const float* __restrict__ emb, const int* __restrict__ eidx,
    const float* __restrict__ W,
    const float* __restrict__ att_s, const float* __restrict__ att_d) {
    extern __shared__ float sm[];
    float* As = sm;                    // [128][132]
    float* Bs = sm + 128 * SA1;        // [128][136]
    int t = blockIdx.y;
    const float* embt = emb + (size_t)t * N_ENT * D;
    const int* idxt = eidx + (size_t)t * N_ENT;
    int tid = threadIdx.x;
    int bm = blockIdx.x * 128;
    uint32_t sbase = (uint32_t)__cvta_generic_to_shared(sm);

#pragma unroll
    for (int i = 0; i < 16; i++) {      // stage B (lin_w 128x128)
        int l = tid + i * 256;
        int row = l >> 5, c4 = l & 31;
        cp16(sbase + (uint32_t)(128 * SA1 + row * SB1 + 4 * c4) * 4, W + row * 128 + 4 * c4);
    }
#pragma unroll
    for (int i = 0; i < 16; i++) {      // stage A (gathered rows)
        int l = tid + i * 256;
        int row = l >> 5, c4 = l & 31;
        int rg = bm + row;
        int srcr = (rg < N_ENT) ? idxt[rg] : 0;
        cp16(sbase + (uint32_t)(row * SA1 + 4 * c4) * 4, embt + (size_t)srcr * D + 4 * c4);
    }
    CP_COMMIT; CP_WAIT0;
    __syncthreads();

    int lane = tid & 31, wid = tid >> 5;
    int wm = (wid & 3) * 32, wn = (wid >> 2) * 64;
    int l4 = lane >> 2, lq = lane & 3;
    float acc[2][8][4];
#pragma unroll
    for (int mt = 0; mt < 2; mt++)
#pragma unroll
        for (int nt = 0; nt < 8; nt++)
#pragma unroll
            for (int q = 0; q < 4; q++) acc[mt][nt][q] = 0.f;

    for (int k0 = 0; k0 < 128; k0 += 8) {
        uint32_t ah[2][4], al[2][4];
#pragma unroll
        for (int mt = 0; mt < 2; mt++) {
            int r = wm + mt * 16 + l4;
            tfsplit(As[r * SA1 + k0 + lq],           ah[mt][0], al[mt][0]);
            tfsplit(As[(r + 8) * SA1 + k0 + lq],     ah[mt][1], al[mt][1]);
            tfsplit(As[r * SA1 + k0 + lq + 4],       ah[mt][2], al[mt][2]);
            tfsplit(As[(r + 8) * SA1 + k0 + lq + 4], ah[mt][3], al[mt][3]);
        }
#pragma unroll
        for (int nt = 0; nt < 8; nt++) {
            int cb = wn + nt * 8 + l4;
            uint32_t b0h, b0l, b1h, b1l;
            tfsplit(Bs[(k0 + lq) * SB1 + cb],     b0h, b0l);
            tfsplit(Bs[(k0 + lq + 4) * SB1 + cb], b1h, b1l);
#pragma unroll
            for (int mt = 0; mt < 2; mt++) {
                mma8(acc[mt][nt], ah[mt], b0h, b1h);
                mma8(acc[mt][nt], al[mt], b0h, b1h);
                mma8(acc[mt][nt], ah[mt], b0l, b1l);
            }
        }
    }
    __syncthreads();
    float* Cs = As;   // reuse
#pragma unroll
    for (int mt = 0; mt < 2; mt++)
#pragma unroll
        for (int nt = 0; nt < 8; nt++) {
            int r = wm + mt * 16 + l4;
            int c = wn + nt * 8 + 2 * lq;
            *(float2*)&Cs[r * SA1 + c] = make_float2(acc[mt][nt][0], acc[mt][nt][1]);
            *(float2*)&Cs[(r + 8) * SA1 + c] = make_float2(acc[mt][nt][2], acc[mt][nt][3]);
        }
    __syncthreads();

    float4 aS = ((const float4*)att_s)[lane];
    float4 aD = ((const float4*)att_d)[lane];
    for (int i = 0; i < 16; i++) {
        int row = wid * 16 + i;
        int rg = bm + row;
        if (rg >= N_ENT) break;
        float4 v = *(float4*)&Cs[row * SA1 + 4 * lane];
        ((float4*)(g_xw + ((size_t)t * N_ENT + rg) * D))[lane] = v;
        float s = v.x * aS.x + v.y * aS.y + v.z * aS.z + v.w * aS.w;
        float d = v.x * aD.x + v.y * aD.y + v.z * aD.z + v.w * aD.w;
#pragma unroll
        for (int off = 16; off; off >>= 1) {
            s += __shfl_xor_sync(0xffffffffu, s, off);
            d += __shfl_xor_sync(0xffffffffu, d, off);
        }
        if (lane == 0) { g_as[t * N_ENT + rg] = s; g_ad[t * N_ENT + rg] = d; }
    }
}

// ================= fused GAT: softmax (no max pass) + aggregate + bias + LN =================
__global__ void k_gat(const float* __restrict__ conv_bias,
                      const float* __restrict__ gamma_all, const float* __restrict__ beta_all) {
    int t = blockIdx.y;
    int dn = blockIdx.x * 8 + (threadIdx.x >> 5);
    if (dn >= N_ENT) return;
    int lane = threadIdx.x & 31;
    const float* asv = g_as + t * N_ENT;
    float ad = g_ad[t * N_ENT + dn];
    int off0 = g_off[t * N_ENT + dn];
    int off1 = (dn + 1 < N_ENT) ? g_off[t * N_ENT + dn + 1] : E_EDGES;
    const int* csr = g_csr + (size_t)t * E_EDGES;

    float ssum = 0.f;
    for (int j = off0 + lane; j < off1; j += 32)
        ssum += __expf(leaky(asv[csr[j]] + ad));
#pragma unroll
    for (int off = 16; off; off >>= 1) ssum += __shfl_xor_sync(0xffffffffu, ssum, off);
    float ex_self = __expf(leaky(asv[dn] + ad));
    float inv = 1.f / (ssum + ex_self + 1e-16f);

    const float* xw = g_xw + (size_t)t * N_ENT * D;
    float a_self = ex_self * inv;
    float4 acc = ((const float4*)(xw + (size_t)dn * D))[lane];
    acc.x *= a_self; acc.y *= a_self; acc.z *= a_self; acc.w *= a_self;
    for (int j = off0; j < off1; j++) {
        int s = csr[j];
        float a = __expf(leaky(asv[s] + ad)) * inv;
        float4 v = ((const float4*)(xw + (size_t)s * D))[lane];
        FMA4(acc, a, v);
    }

    float4 cb = ((const float4*)conv_bias)[lane];
    acc.x += cb.x; acc.y += cb.y; acc.z += cb.z; acc.w += cb.w;
    float sum = acc.x + acc.y + acc.z + acc.w;
#pragma unroll
    for (int off = 16; off; off >>= 1) sum += __shfl_xor_sync(0xffffffffu, sum, off);
    float mu = sum * (1.f / D);
    float4 dd = make_float4(acc.x - mu, acc.y - mu, acc.z - mu, acc.w - mu);
    float sq = dd.x * dd.x + dd.y * dd.y + dd.z * dd.z + dd.w * dd.w;
#pragma unroll
    for (int off = 16; off; off >>= 1) sq += __shfl_xor_sync(0xffffffffu, sq, off);
    float invs = rsqrtf(sq * (1.f / D) + LN_EPS);
    float4 gm = ((const float4*)(gamma_all + t * D))[lane];
    float4 bt = ((const float4*)(beta_all + t * D))[lane];
    float4 h;
    h.x = dd.x * invs * gm.x + bt.x;
    h.y = dd.y * invs * gm.y + bt.y;
    h.z = dd.z * invs * gm.z + bt.z;
    h.w = dd.w * invs * gm.w + bt.w;
    ((float4*)(g_h + ((size_t)t * N_ENT + dn) * D))[lane] = h;
}

// ================= msg gather into combined buffer =================
__global__ void k_msg() {
    int t = blockIdx.y;
    int dn = blockIdx.x * 8 + (threadIdx.x >> 5);
    if (dn >= N_TX) return;
    int lane = threadIdx.x & 31;
    int off0 = g_off[t * N_ENT + dn];
    int off1 = (dn + 1 < N_ENT) ? g_off[t * N_ENT + dn + 1] : E_EDGES;
    const int* csr = g_csr + (size_t)t * E_EDGES;
    const float* h = g_h + (size_t)t * N_ENT * D;
    float4 acc = make_float4(0.f, 0.f, 0.f, 0.f);
    for (int j = off0; j < off1; j++) {
        float4 v = ((const float4*)(h + (size_t)csr[j] * D))[lane];
        acc.x += v.x; acc.y += v.y; acc.z += v.z; acc.w += v.w;
    }
    ((float4*)(g_comb + (size_t)dn * COMB_STRIDE + t * D))[lane] = acc;
}

// ================= classifier layer 1 (3xTF32 mma, double-buffered cp.async) =================
#define SA2 36
#define SB2 136
#define NIT 57   /* 1824 / 32 */
__device__ __forceinline__ void h1_stage(uint32_t abase, uint32_t bbase, int kc, int bm,
                                         int tid, const float* __restrict__ w1) {
#pragma unroll
    for (int i = 0; i < 4; i++) {       // A: 128 rows x 8 float4
        int l = tid + i * 256;
        int row = l >> 3, c4 = l & 7;
        int rg = bm + row;
        if (rg >= N_TX) rg = 0;
        cp16(abase + (uint32_t)(row * SA2 + 4 * c4) * 4,
             g_comb + (size_t)rg * COMB_STRIDE + kc + 4 * c4);
    }
#pragma unroll
    for (int i = 0; i < 4; i++) {       // B: 32 k x 32 float4
        int l = tid + i * 256;
        int kk = l >> 5, c4 = l & 31;
        int ck = kc + kk;
        uint32_t daddr = bbase + (uint32_t)(kk * SB2 + 4 * c4) * 4;
        if (ck < 1408)          cp16(daddr, w1 + (size_t)(394 + ck) * D + 4 * c4);
        else if (ck < COMB_K)   cp16(daddr, w1 + (size_t)(ck - 1408) * D + 4 * c4);
        else                    cp16z(daddr, w1);
    }
}

__global__ __launch_bounds__(256, 2) void k_h1(const float* __restrict__ w1,
                                               const float* __restrict__ b1) {
    extern __shared__ float sm[];
    int tid = threadIdx.x;
    int bm = blockIdx.x * 128;
    uint32_t sbase = (uint32_t)__cvta_generic_to_shared(sm);
    uint32_t aB[2] = {sbase, sbase + (uint32_t)(128 * SA2) * 4};
    uint32_t bB[2] = {sbase + (uint32_t)(2 * 128 * SA2) * 4,
                      sbase + (uint32_t)(2 * 128 * SA2 + 32 * SB2) * 4};
    const float* Ap[2] = {sm, sm + 128 * SA2};
    const float* Bp[2] = {sm + 2 * 128 * SA2, sm + 2 * 128 * SA2 + 32 * SB2};

    int lane = tid & 31, wid = tid >> 5;
    int wm = (wid & 3) * 32, wn = (wid >> 2) * 64;
    int l4 = lane >> 2, lq = lane & 3;
    float acc[2][8][4];
#pragma unroll
    for (int mt = 0; mt < 2; mt++)
#pragma unroll
        for (int nt = 0; nt < 8; nt++)
#pragma unroll
            for (int q = 0; q < 4; q++) acc[mt][nt][q] = 0.f;

    h1_stage(aB[0], bB[0], 0, bm, tid, w1);
    CP_COMMIT;

    for (int it = 0; it < NIT; it++) {
        int cur = it & 1;
        CP_WAIT0;
        __syncthreads();
        if (it + 1 < NIT) {
            h1_stage(aB[1 - cur], bB[1 - cur], (it + 1) * 32, bm, tid, w1);
            CP_COMMIT;
        }
        const float* Af = Ap[cur];
        const float* Bf = Bp[cur];
#pragma unroll
        for (int ks = 0; ks < 4; ks++) {
            int k0 = ks * 8;
            uint32_t ah[2][4], al[2][4];
#pragma unroll
            for (int mt = 0; mt < 2; mt++) {
                int r = wm + mt * 16 + l4;
                tfsplit(Af[r * SA2 + k0 + lq],           ah[mt][0], al[mt][0]);
                tfsplit(Af[(r + 8) * SA2 + k0 + lq],     ah[mt][1], al[mt][1]);
                tfsplit(Af[r * SA2 + k0 + lq + 4],       ah[mt][2], al[mt][2]);
                tfsplit(Af[(r + 8) * SA2 + k0 + lq + 4], ah[mt][3], al[mt][3]);
            }
#pragma unroll
            for (int nt = 0; nt < 8; nt++) {
                int cb = wn + nt * 8 + l4;
                uint32_t b0h, b0l, b1h, b1l;
                tfsplit(Bf[(k0 + lq) * SB2 + cb],     b0h, b0l);
                tfsplit(Bf[(k0 + lq + 4) * SB2 + cb], b1h, b1l);
#pragma unroll
                for (int mt = 0; mt < 2; mt++) {
                    mma8(acc[mt][nt], ah[mt], b0h, b1h);
                    mma8(acc[mt][nt], al[mt], b0h, b1h);
                    mma8(acc[mt][nt], ah[mt], b0l, b1l);
                }
            }
        }
        __syncthreads();
    }

#pragma unroll
    for (int mt = 0; mt < 2; mt++)
#pragma unroll
        for (int nt = 0; nt < 8; nt++) {
            int r = bm + wm + mt * 16 + l4;
            int c = wn + nt * 8 + 2 * lq;
            float2 bb = *(const float2*)(b1 + c);
            if (r < N_TX)
                *(float2*)&g_h1[(size_t)r * D + c] =
                    make_float2(fmaxf(acc[mt][nt][0] + bb.x, 0.f),
                                fmaxf(acc[mt][nt][1] + bb.y, 0.f));
            if (r + 8 < N_TX)
                *(float2*)&g_h1[(size_t)(r + 8) * D + c] =
                    make_float2(fmaxf(acc[mt][nt][2] + bb.x, 0.f),
                                fmaxf(acc[mt][nt][3] + bb.y, 0.f));
        }
}

// ================= fused classifier layers 2+3 =================
__global__ void k_h23(const float* __restrict__ w2, const float* __restrict__ b2,
                      const float* __restrict__ w3, const float* __restrict__ b3,
                      float* __restrict__ out) {
    __shared__ float Ws[128 * 64];
    __shared__ float w3s[64];
    int tid = threadIdx.x;
#pragma unroll
    for (int i = 0; i < 8; i++)
        ((float4*)Ws)[tid + i * 256] = ((const float4*)w2)[tid + i * 256];
    if (tid < 64) w3s[tid] = w3[tid];
    __syncthreads();
    int lane = tid & 31, w = tid >> 5;
    for (int rr = 0; rr < 4; rr++) {
        int r = blockIdx.x * 32 + rr * 8 + w;
        if (r >= N_TX) return;
        float4 x = ((const float4*)(g_h1 + (size_t)r * D))[lane];
        float xa[4] = {x.x, x.y, x.z, x.w};
        float a0 = 0.f, a1 = 0.f;
#pragma unroll
        for (int k = 0; k < 128; k++) {
            float xk = __shfl_sync(0xffffffffu, xa[k & 3], k >> 2);
            float2 wv = *(const float2*)&Ws[k * 64 + lane * 2];
            a0 += xk * wv.x;
            a1 += xk * wv.y;
        }
        float2 bb = *(const float2*)&b2[lane * 2];
        float h0 = fmaxf(a0 + bb.x, 0.f);
        float h1v = fmaxf(a1 + bb.y, 0.f);
        float v = h0 * w3s[lane * 2] + h1v * w3s[lane * 2 + 1];
#pragma unroll
        for (int off = 16; off; off >>= 1) v += __shfl_xor_sync(0xffffffffu, v, off);
        if (lane == 0) out[r] = v + b3[0];
    }
}

// ================= launcher =================
extern "C" void kernel_launch(void* const* d_in, const int* in_sizes, int n_in,
                              void* d_out, int out_size) {
    const float* tx_x      = (const float*)d_in[0];
    const float* emb       = (const float*)d_in[1];
    const float* lin_w     = (const float*)d_in[2];
    const float* att_src   = (const float*)d_in[3];
    const float* att_dst   = (const float*)d_in[4];
    const float* conv_bias = (const float*)d_in[5];
    const float* ln_gamma  = (const float*)d_in[6];
    const float* ln_beta   = (const float*)d_in[7];
    const float* w1        = (const float*)d_in[8];
    const float* b1        = (const float*)d_in[9];
    const float* w2        = (const float*)d_in[10];
    const float* b2        = (const float*)d_in[11];
    const float* w3        = (const float*)d_in[12];
    const float* b3        = (const float*)d_in[13];
    const int* entity_idx  = (const int*)d_in[14];
    const int* edge_src    = (const int*)d_in[15];
    const int* edge_dst    = (const int*)d_in[16];
    float* out = (float*)d_out;

    cudaFuncSetAttribute(k_gemm1, cudaFuncAttributeMaxDynamicSharedMemorySize,
                         (128 * SA1 + 128 * SB1) * 4);
    cudaFuncSetAttribute(k_h1, cudaFuncAttributeMaxDynamicSharedMemorySize,
                         (2 * 128 * SA2 + 2 * 32 * SB2) * 4);

    // ---- CSR build ----
    k_zero_cnt<<<(T * N_ENT + 255) / 256, 256>>>();
    { dim3 g((E_EDGES + 255) / 256, T); k_hist<<<g, 256>>>(edge_dst); }
    { dim3 g(NBLK_SCAN, T); k_scan1<<<g, SCAN_BLK>>>(); }
    k_scan2<<<T, 32>>>();
    { dim3 g(NBLK_SCAN, T); k_scan3<<<g, SCAN_BLK>>>(); }
    { dim3 g((E_EDGES + 255) / 256, T); k_fill<<<g, 256>>>(edge_src, edge_dst); }

    // ---- tx into combined buffer (independent) ----
    k_copytx<<<(N_TX + 7) / 8, 256>>>(tx_x);

    // ---- batched GAT pipeline ----
    { dim3 g((N_ENT + 127) / 128, T);
      k_gemm1<<<g, 256, (128 * SA1 + 128 * SB1) * 4>>>(emb, entity_idx, lin_w, att_src, att_dst); }
    { dim3 g((N_ENT + 7) / 8, T); k_gat<<<g, 256>>>(conv_bias, ln_gamma, ln_beta); }
    { dim3 g((N_TX + 7) / 8, T); k_msg<<<g, 256>>>(); }

    // ---- classifier ----
    k_h1<<<(N_TX + 127) / 128, 256, (2 * 128 * SA2 + 2 * 32 * SB2) * 4>>>(w1, b1);
    k_h23<<<(N_TX + 31) / 32, 256>>>(w2, b2, w3, b3, out);
}